// round 1
// baseline (speedup 1.0000x reference)
#include <cuda_runtime.h>
#include <stdint.h>

// ============================================================================
// L2Loss with class-rebalancing weights (colorization loss).
//   loss = mean_b sum_{c,h,w} (input - target)^2 * implied_prior[argmin_q d2(target_pixel, ab_gamut[q])]
//
// Strategy: exact nearest-neighbor via uniform-grid candidate LUT.
//   Kernel 1 (build_lut): for each of 64x64 cells over [-1,1]^2, find all bins
//     with d(center,bin) <= dmin(center) + 2r  (r = cell half-diagonal).
//     This set provably contains the true NN of every point in the cell.
//   Kernel 2 (loss): per pixel, scan the (tiny) candidate list with a packed
//     (score,idx) umin argmin; weighted L2; hierarchical reduce + atomicAdd.
// ============================================================================

#define LGRID 64
#define CAP   32
#define MAXQ  512   // shared-array capacity; actual Q = 313

__device__ unsigned short g_cand[LGRID * LGRID * CAP];
__device__ unsigned int   g_cnt[LGRID * LGRID];

// ---------------------------------------------------------------------------
// Build the candidate LUT. One warp per cell. 512 blocks x 256 threads = 4096 warps.
// Candidate order is deterministic (ballot compaction, ascending bin index).
// ---------------------------------------------------------------------------
__global__ void __launch_bounds__(256) build_lut_kernel(
    const float2* __restrict__ gamut, int Q)
{
    __shared__ float2 sg[MAXQ];
    for (int i = threadIdx.x; i < Q; i += blockDim.x) sg[i] = gamut[i];
    __syncthreads();

    const int warp = threadIdx.x >> 5;
    const int lane = threadIdx.x & 31;
    const int cell = blockIdx.x * (blockDim.x >> 5) + warp;
    if (cell >= LGRID * LGRID) return;

    const int ix = cell & (LGRID - 1);
    const int iy = cell >> 6;                 // log2(LGRID)
    const float cellw = 2.0f / (float)LGRID;
    const float cx = -1.0f + ((float)ix + 0.5f) * cellw;
    const float cy = -1.0f + ((float)iy + 0.5f) * cellw;
    // 2r = full diagonal = cellw * sqrt(2) = 0.044194 for LGRID=64; pad for FP slop.
    const float two_r = 0.04450f;

    float d2s[(MAXQ + 31) / 32];
    float dmin = 1e30f;
    const int nIter = (Q + 31) >> 5;
    #pragma unroll
    for (int j = 0; j < (MAXQ + 31) / 32; j++) {
        if (j >= nIter) break;
        const int b = (j << 5) + lane;
        float d2 = 1e30f;
        if (b < Q) {
            const float dx = sg[b].x - cx;
            const float dy = sg[b].y - cy;
            d2 = fmaf(dx, dx, dy * dy);
        }
        d2s[j] = d2;
        dmin = fminf(dmin, d2);
    }
    #pragma unroll
    for (int off = 16; off; off >>= 1)
        dmin = fminf(dmin, __shfl_xor_sync(0xFFFFFFFFu, dmin, off));

    const float s   = sqrtf(dmin) + two_r;
    const float thr = fmaf(s, s, 1e-6f) * 1.00002f;

    int base = 0;
    for (int j = 0; j < nIter; j++) {
        const bool take = (d2s[j] <= thr);
        const unsigned m = __ballot_sync(0xFFFFFFFFu, take);
        if (take) {
            const int pos = base + __popc(m & ((1u << lane) - 1u));
            if (pos < CAP)
                g_cand[cell * CAP + pos] = (unsigned short)((j << 5) + lane);
        }
        base += __popc(m);
    }
    if (lane == 0) g_cnt[cell] = (unsigned)base;  // >CAP triggers full-scan fallback
}

// ---------------------------------------------------------------------------
// Main loss kernel. 2 pixels/thread. 512 blocks x 256 threads covers 262144 px.
// Layout [b, 2, 256, 256]: pixel q -> b = q>>16, n = q&65535,
//   ch0 at b*131072 + n, ch1 at +65536.
// Argmin key: score shifted positive (c = |g|^2 + 16 => score in [12.6, 20.9]),
//   key = (bits(score) & ~0x1FF) | bin_idx, umin -> argmin with low-index ties.
// ---------------------------------------------------------------------------
__global__ void __launch_bounds__(256) loss_kernel(
    const float*  __restrict__ input,
    const float*  __restrict__ target,
    const float2* __restrict__ gamut,
    const float*  __restrict__ prior,
    float*        __restrict__ out,
    int Q, int inv_b_num /*unused*/)
{
    __shared__ float4 sf[MAXQ];   // (ha=-2gx, hb=-2gy, c=|g|^2+16, prior)
    for (int i = threadIdx.x; i < Q; i += blockDim.x) {
        const float2 g = gamut[i];
        sf[i] = make_float4(-2.0f * g.x, -2.0f * g.y,
                            fmaf(g.x, g.x, fmaf(g.y, g.y, 16.0f)),
                            prior[i]);
    }
    __syncthreads();

    const int tid     = blockIdx.x * blockDim.x + threadIdx.x;
    const int nthread = gridDim.x * blockDim.x;   // 131072
    float acc = 0.0f;

    #pragma unroll
    for (int pp = 0; pp < 2; pp++) {
        const int q     = tid + pp * nthread;     // 0 .. 262143
        const int bb    = q >> 16;
        const int n     = q & 65535;
        const int base0 = bb * 131072 + n;

        const float t0 = target[base0];
        const float t1 = target[base0 + 65536];
        const float i0 = input[base0];
        const float i1 = input[base0 + 65536];

        int ix = (int)((t0 + 1.0f) * ((float)LGRID * 0.5f));
        int iy = (int)((t1 + 1.0f) * ((float)LGRID * 0.5f));
        ix = min(max(ix, 0), LGRID - 1);
        iy = min(max(iy, 0), LGRID - 1);
        const int cell = iy * LGRID + ix;

        const unsigned cnt = g_cnt[cell];
        unsigned best = 0xFFFFFFFFu;

        if (cnt <= CAP) {
            const unsigned short* cl = &g_cand[cell * CAP];
            for (unsigned j = 0; j < cnt; j++) {
                const unsigned bi = (unsigned)cl[j];
                const float4 g = sf[bi];
                const float sc = fmaf(g.x, t0, fmaf(g.y, t1, g.z));
                const unsigned key = (__float_as_uint(sc) & 0xFFFFFE00u) | bi;
                best = min(best, key);
            }
        } else {
            // exact fallback (never expected to trigger with CAP=32)
            for (int bi = 0; bi < Q; bi++) {
                const float4 g = sf[bi];
                const float sc = fmaf(g.x, t0, fmaf(g.y, t1, g.z));
                const unsigned key = (__float_as_uint(sc) & 0xFFFFFE00u) | (unsigned)bi;
                best = min(best, key);
            }
        }

        const float w  = sf[best & (MAXQ - 1)].w;
        const float d0 = i0 - t0;
        const float d1 = i1 - t1;
        acc += w * fmaf(d0, d0, d1 * d1);
    }

    acc *= 0.25f;   // mean over b = 4  (sum_total / 4)

    // warp reduce
    #pragma unroll
    for (int off = 16; off; off >>= 1)
        acc += __shfl_xor_sync(0xFFFFFFFFu, acc, off);

    __shared__ float ws[8];
    if ((threadIdx.x & 31) == 0) ws[threadIdx.x >> 5] = acc;
    __syncthreads();
    if (threadIdx.x < 8) {
        float v = ws[threadIdx.x];
        #pragma unroll
        for (int off = 4; off; off >>= 1)
            v += __shfl_xor_sync(0xFFu, v, off);
        if (threadIdx.x == 0) atomicAdd(out, v);
    }
}

// ---------------------------------------------------------------------------
extern "C" void kernel_launch(void* const* d_in, const int* in_sizes, int n_in,
                              void* d_out, int out_size)
{
    const float*  input  = (const float*)d_in[0];
    const float*  target = (const float*)d_in[1];
    const float2* gamut  = (const float2*)d_in[2];   // [Q,2]
    const float*  prior  = (const float*)d_in[3];    // [Q]
    float* out = (float*)d_out;
    const int Q = in_sizes[3];                        // 313

    // zero the scalar accumulator (d_out is poisoned)
    cudaMemsetAsync(out, 0, sizeof(float));

    // build candidate LUT: 4096 cells, one warp each
    build_lut_kernel<<<(LGRID * LGRID) / 8, 256>>>(gamut, Q);

    // main loss: 262144 pixels, 2 per thread
    loss_kernel<<<512, 256>>>(input, target, gamut, prior, out, Q, 4);
}